// round 15
// baseline (speedup 1.0000x reference)
#include <cuda_runtime.h>
#include <cuda_fp16.h>
#include <cstddef>
#include <cstdint>

#define N_NODES 100000
#define N_EDGES 1000000
#define G_GRAPHS 1024
#define S_SUB 128
#define HID 64
#define EDGE_F 32
#define OUT_F 32
#define L_LAYERS 3
#define BN_EPS 1e-5f

#define E_TILE 128
#define E_TILES_TOTAL 7813
#define E_GRID 1024
#define N_TILES 1563
#define N_GRID 1563            // one tile per block: grid supplies full occupancy

#define ST20 20
#define ST36 36
#define SF 68

// ---------------- device scratch ----------------
__device__ uint32_t d_zh[N_NODES * 32];        // node state, half2-packed
__device__ float d_agg[N_NODES * HID];
__device__ float d_bnsum[L_LAYERS * 2 * HID];
__device__ float d_gsum[G_GRAPHS * L_LAYERS * HID];
__device__ float d_gcnt[G_GRAPHS];
__device__ float d_svec[S_SUB * HID];
__device__ float d_snorm[S_SUB];
__device__ float d_t1[S_SUB * HID];
__device__ float d_t2[S_SUB * HID];

__device__ __forceinline__ void red4(float* addr, float4 v) {
    asm volatile("red.global.add.v4.f32 [%0], {%1,%2,%3,%4};"
                 :: "l"(addr), "f"(v.x), "f"(v.y), "f"(v.z), "f"(v.w)
                 : "memory");
}

__device__ __forceinline__ uint32_t packh2(float lo, float hi) {
    __half2 h = __floats2half2_rn(lo, hi);
    return *reinterpret_cast<uint32_t*>(&h);
}

__device__ __forceinline__ float2 unpackh2(uint32_t u) {
    return __half22float2(*reinterpret_cast<__half2*>(&u));
}

__device__ __forceinline__ void mma16(float* d, uint32_t a0, uint32_t a1,
                                      uint32_t a2, uint32_t a3,
                                      uint32_t b0, uint32_t b1) {
    asm volatile(
        "mma.sync.aligned.m16n8k16.row.col.f32.f16.f16.f32 "
        "{%0,%1,%2,%3}, {%4,%5,%6,%7}, {%8,%9}, {%0,%1,%2,%3};"
        : "+f"(d[0]), "+f"(d[1]), "+f"(d[2]), "+f"(d[3])
        : "r"(a0), "r"(a1), "r"(a2), "r"(a3), "r"(b0), "r"(b1));
}

// ---------------- init ----------------
__global__ void count_kernel(const int* __restrict__ batch) {
    int i = blockIdx.x * 256 + threadIdx.x;
    if (i < N_NODES) atomicAdd(&d_gcnt[batch[i]], 1.0f);
}

__global__ void z_init_kernel(const float* __restrict__ x) {
    int i = blockIdx.x * 256 + threadIdx.x;
    float2 v = ((const float2*)x)[i];
    d_zh[i] = packh2(v.x, v.y);
}

// =====================================================================
// Fused edge kernel (round-13 version, unchanged)
// =====================================================================
#define E_SMEM_BYTES ((64*ST20 + 64*ST36 + 256 + 128*ST20 + 128*ST36) * 4)

__global__ __launch_bounds__(128)
void edge_kernel(const float* __restrict__ edge_attr,
                 const int* __restrict__ eidx,
                 const float* __restrict__ w1, const float* __restrict__ b1,
                 const float* __restrict__ w2, const float* __restrict__ b2,
                 const float* __restrict__ bnsum_prev,
                 const float* __restrict__ gamma_prev,
                 const float* __restrict__ beta_prev, int useBN) {
    extern __shared__ float smem[];
    uint32_t* sW1t = (uint32_t*)smem;
    uint32_t* sW2t = sW1t + 64 * ST20;
    float* sB1 = (float*)(sW2t + 64 * ST36);
    float* sB2 = sB1 + 64;
    float* sAB = sB2 + 64;
    uint32_t* sAh = (uint32_t*)(sAB + 128);
    uint32_t* sHh = sAh + 128 * ST20;

    const int tid = threadIdx.x;
    const int lane = tid & 31, warp = tid >> 5;
    const int quad = lane >> 2, tq = lane & 3;
    const int r0 = warp * 32;
    const int tc = tid & 7, tr = tid >> 3;
    const int cc = tc * 8;

    for (int i = tid; i < 1024; i += 128) {
        int n = i & 63, j = i >> 6;
        sW1t[n * ST20 + j] = packh2(w1[(2 * j) * 64 + n], w1[(2 * j + 1) * 64 + n]);
    }
    for (int i = tid; i < 2048; i += 128) {
        int n = i & 63, j = i >> 6;
        sW2t[n * ST36 + j] = packh2(w2[(2 * j) * 64 + n], w2[(2 * j + 1) * 64 + n]);
    }
    if (tid < 64) {
        sB1[tid] = b1[tid]; sB2[tid] = b2[tid];
        float a = 1.f, b = 0.f;
        if (useBN) {
            float mu = bnsum_prev[tid] * (1.f / (float)N_NODES);
            float var = bnsum_prev[64 + tid] * (1.f / (float)N_NODES) - mu * mu;
            a = gamma_prev[tid] * rsqrtf(var + BN_EPS);
            b = beta_prev[tid] - mu * a;
        }
        sAB[tid] = a; sAB[64 + tid] = b;
    }
    __syncthreads();

    const float4 ax0 = *((const float4*)(sAB + cc));
    const float4 ax1 = *((const float4*)(sAB + cc + 4));
    const float4 bx0 = *((const float4*)(sAB + 64 + cc));
    const float4 bx1 = *((const float4*)(sAB + 64 + cc + 4));

    for (int tile = blockIdx.x; tile < E_TILES_TOTAL; tile += E_GRID) {
        const int e0 = tile * E_TILE;

        for (int i = tid; i < 1024; i += 128) {
            int r = i >> 3, q = i & 7;
            float4 v = make_float4(0.f, 0.f, 0.f, 0.f);
            if (e0 + r < N_EDGES)
                v = ((const float4*)(edge_attr + (size_t)(e0 + r) * EDGE_F))[q];
            sAh[r * ST20 + q * 2]     = packh2(v.x, v.y);
            sAh[r * ST20 + q * 2 + 1] = packh2(v.z, v.w);
        }
        __syncthreads();

        float acc[2][8][4];
#pragma unroll
        for (int m = 0; m < 2; ++m)
#pragma unroll
            for (int nt = 0; nt < 8; ++nt)
#pragma unroll
                for (int j = 0; j < 4; ++j) acc[m][nt][j] = 0.f;

#pragma unroll
        for (int ks = 0; ks < 2; ++ks) {
            uint32_t A[2][4];
#pragma unroll
            for (int m = 0; m < 2; ++m) {
                int rb = r0 + 16 * m;
                A[m][0] = sAh[(rb + quad) * ST20 + ks * 8 + tq];
                A[m][1] = sAh[(rb + quad + 8) * ST20 + ks * 8 + tq];
                A[m][2] = sAh[(rb + quad) * ST20 + ks * 8 + tq + 4];
                A[m][3] = sAh[(rb + quad + 8) * ST20 + ks * 8 + tq + 4];
            }
#pragma unroll
            for (int nt = 0; nt < 8; ++nt) {
                uint32_t b0 = sW1t[(nt * 8 + quad) * ST20 + ks * 8 + tq];
                uint32_t b1v = sW1t[(nt * 8 + quad) * ST20 + ks * 8 + tq + 4];
#pragma unroll
                for (int m = 0; m < 2; ++m)
                    mma16(acc[m][nt], A[m][0], A[m][1], A[m][2], A[m][3], b0, b1v);
            }
        }

#pragma unroll
        for (int m = 0; m < 2; ++m) {
            int rb = r0 + 16 * m;
#pragma unroll
            for (int nt = 0; nt < 8; ++nt) {
                int c = nt * 8 + 2 * tq;
                sHh[(rb + quad) * ST36 + nt * 4 + tq] =
                    packh2(fmaxf(acc[m][nt][0] + sB1[c], 0.f),
                           fmaxf(acc[m][nt][1] + sB1[c + 1], 0.f));
                sHh[(rb + quad + 8) * ST36 + nt * 4 + tq] =
                    packh2(fmaxf(acc[m][nt][2] + sB1[c], 0.f),
                           fmaxf(acc[m][nt][3] + sB1[c + 1], 0.f));
            }
        }
        __syncwarp();

#pragma unroll
        for (int m = 0; m < 2; ++m)
#pragma unroll
            for (int nt = 0; nt < 8; ++nt)
#pragma unroll
                for (int j = 0; j < 4; ++j) acc[m][nt][j] = 0.f;

#pragma unroll
        for (int ks = 0; ks < 4; ++ks) {
            uint32_t A[2][4];
#pragma unroll
            for (int m = 0; m < 2; ++m) {
                int rb = r0 + 16 * m;
                A[m][0] = sHh[(rb + quad) * ST36 + ks * 8 + tq];
                A[m][1] = sHh[(rb + quad + 8) * ST36 + ks * 8 + tq];
                A[m][2] = sHh[(rb + quad) * ST36 + ks * 8 + tq + 4];
                A[m][3] = sHh[(rb + quad + 8) * ST36 + ks * 8 + tq + 4];
            }
#pragma unroll
            for (int nt = 0; nt < 8; ++nt) {
                uint32_t b0 = sW2t[(nt * 8 + quad) * ST36 + ks * 8 + tq];
                uint32_t b1v = sW2t[(nt * 8 + quad) * ST36 + ks * 8 + tq + 4];
#pragma unroll
                for (int m = 0; m < 2; ++m)
                    mma16(acc[m][nt], A[m][0], A[m][1], A[m][2], A[m][3], b0, b1v);
            }
        }
        __syncwarp();

#pragma unroll
        for (int m = 0; m < 2; ++m) {
            int rb = r0 + 16 * m;
#pragma unroll
            for (int nt = 0; nt < 8; ++nt) {
                int c = nt * 8 + 2 * tq;
                sHh[(rb + quad) * ST36 + nt * 4 + tq] =
                    packh2(acc[m][nt][0] + sB2[c], acc[m][nt][1] + sB2[c + 1]);
                sHh[(rb + quad + 8) * ST36 + nt * 4 + tq] =
                    packh2(acc[m][nt][2] + sB2[c], acc[m][nt][3] + sB2[c + 1]);
            }
        }
        __syncthreads();

#pragma unroll
        for (int i = 0; i < 8; ++i) {
            int r = tr * 8 + i;
            int e = e0 + r;
            if (e < N_EDGES) {
                int src = eidx[e];
                int dst = eidx[N_EDGES + e];
                uint4 hu = *(const uint4*)(d_zh + (size_t)src * 32 + tc * 4);
                float2 h01 = unpackh2(hu.x), h23 = unpackh2(hu.y);
                float2 h45 = unpackh2(hu.z), h67 = unpackh2(hu.w);
                uint4 eu = *(const uint4*)(sHh + r * ST36 + tc * 4);
                float2 e01 = unpackh2(eu.x), e23 = unpackh2(eu.y);
                float2 e45 = unpackh2(eu.z), e67 = unpackh2(eu.w);
                float4 m0, m1;
                m0.x = fmaxf(fmaf(h01.x, ax0.x, bx0.x) + e01.x, 0.f);
                m0.y = fmaxf(fmaf(h01.y, ax0.y, bx0.y) + e01.y, 0.f);
                m0.z = fmaxf(fmaf(h23.x, ax0.z, bx0.z) + e23.x, 0.f);
                m0.w = fmaxf(fmaf(h23.y, ax0.w, bx0.w) + e23.y, 0.f);
                m1.x = fmaxf(fmaf(h45.x, ax1.x, bx1.x) + e45.x, 0.f);
                m1.y = fmaxf(fmaf(h45.y, ax1.y, bx1.y) + e45.y, 0.f);
                m1.z = fmaxf(fmaf(h67.x, ax1.z, bx1.z) + e67.x, 0.f);
                m1.w = fmaxf(fmaf(h67.y, ax1.w, bx1.w) + e67.y, 0.f);
                red4(d_agg + (size_t)dst * HID + cc, m0);
                red4(d_agg + (size_t)dst * HID + cc + 4, m1);
            }
        }
    }
}

// =====================================================================
// Fused node kernel (round-13 version; grid now covers all tiles)
// =====================================================================
#define N_SMEM_BYTES ((64*ST36 + 64*ST36 + 256 + 128 + 64*ST36 + 64*ST36 + 64*SF) * 4)

__global__ __launch_bounds__(128)
void node_kernel(const float* __restrict__ w1, const float* __restrict__ b1,
                 const float* __restrict__ w2, const float* __restrict__ b2,
                 const float* __restrict__ epsp,
                 const float* __restrict__ bnsum_prev,
                 const float* __restrict__ gamma_prev,
                 const float* __restrict__ beta_prev, int useBN,
                 int layer, const int* __restrict__ batch) {
    extern __shared__ float smem[];
    uint32_t* sW1t = (uint32_t*)smem;            // [64][36]
    uint32_t* sW2t = sW1t + 64 * ST36;           // [64][36]
    float* sB1 = (float*)(sW2t + 64 * ST36);
    float* sB2 = sB1 + 64;
    float* sSum = sB2 + 64;
    float* sSq  = sSum + 64;
    float* sAB  = sSq + 64;                      // [128]
    uint32_t* sAh = (uint32_t*)(sAB + 128);      // [64][36]
    uint32_t* sHh = sAh + 64 * ST36;             // [64][36]
    float* sHf = (float*)(sHh + 64 * ST36);      // [64][68]

    const int tid = threadIdx.x;
    const int lane = tid & 31, warp = tid >> 5;
    const int quad = lane >> 2, tq = lane & 3;
    const int r0 = warp * 16;
    const int tc = tid & 7, tr = tid >> 3;
    const int cc = tc * 8, rr = tr * 4;
    const float epl = 1.f + epsp[0];

    for (int i = tid; i < 2048; i += 128) {
        int n = i & 63, j = i >> 6;
        sW1t[n * ST36 + j] = packh2(w1[(2 * j) * 64 + n], w1[(2 * j + 1) * 64 + n]);
    }
    for (int i = tid; i < 2048; i += 128) {
        int n = i & 63, j = i >> 6;
        sW2t[n * ST36 + j] = packh2(w2[(2 * j) * 64 + n], w2[(2 * j + 1) * 64 + n]);
    }
    if (tid < 64) {
        sB1[tid] = b1[tid]; sB2[tid] = b2[tid];
        sSum[tid] = 0.f; sSq[tid] = 0.f;
        float a = 1.f, b = 0.f;
        if (useBN) {
            float mu = bnsum_prev[tid] * (1.f / (float)N_NODES);
            float var = bnsum_prev[64 + tid] * (1.f / (float)N_NODES) - mu * mu;
            a = gamma_prev[tid] * rsqrtf(var + BN_EPS);
            b = beta_prev[tid] - mu * a;
        }
        sAB[tid] = a; sAB[64 + tid] = b;
    }
    __syncthreads();

    float csum[8], csq[8];
#pragma unroll
    for (int j = 0; j < 8; ++j) { csum[j] = 0.f; csq[j] = 0.f; }

    for (int tile = blockIdx.x; tile < N_TILES; tile += N_GRID) {
        const int n0 = tile * 64;

        for (int i = tid; i < 512; i += 128) {
            int r = i >> 3, q = i & 7;
            int n = n0 + r;
            float v[8] = {0.f, 0.f, 0.f, 0.f, 0.f, 0.f, 0.f, 0.f};
            if (n < N_NODES) {
                uint4 zu = ((const uint4*)(d_zh + (size_t)n * 32))[q];
                float2 z01 = unpackh2(zu.x), z23 = unpackh2(zu.y);
                float2 z45 = unpackh2(zu.z), z67 = unpackh2(zu.w);
                float zv[8] = {z01.x, z01.y, z23.x, z23.y,
                               z45.x, z45.y, z67.x, z67.y};
                float4 av0 = ((const float4*)(d_agg + (size_t)n * HID))[q * 2];
                float4 av1 = ((const float4*)(d_agg + (size_t)n * HID))[q * 2 + 1];
                float avv[8] = {av0.x, av0.y, av0.z, av0.w,
                                av1.x, av1.y, av1.z, av1.w};
                const float* aa = sAB + q * 8;
                const float* bb = sAB + 64 + q * 8;
#pragma unroll
                for (int j = 0; j < 8; ++j)
                    v[j] = fmaf(zv[j], epl * aa[j], epl * bb[j]) + avv[j];
            }
            uint32_t* d = sAh + r * ST36 + q * 4;
            d[0] = packh2(v[0], v[1]); d[1] = packh2(v[2], v[3]);
            d[2] = packh2(v[4], v[5]); d[3] = packh2(v[6], v[7]);
        }
        __syncthreads();

        float acc[8][4];
#pragma unroll
        for (int nt = 0; nt < 8; ++nt)
#pragma unroll
            for (int j = 0; j < 4; ++j) acc[nt][j] = 0.f;

#pragma unroll
        for (int ks = 0; ks < 4; ++ks) {
            uint32_t a0 = sAh[(r0 + quad) * ST36 + ks * 8 + tq];
            uint32_t a1 = sAh[(r0 + quad + 8) * ST36 + ks * 8 + tq];
            uint32_t a2 = sAh[(r0 + quad) * ST36 + ks * 8 + tq + 4];
            uint32_t a3 = sAh[(r0 + quad + 8) * ST36 + ks * 8 + tq + 4];
#pragma unroll
            for (int nt = 0; nt < 8; ++nt) {
                uint32_t b0 = sW1t[(nt * 8 + quad) * ST36 + ks * 8 + tq];
                uint32_t b1v = sW1t[(nt * 8 + quad) * ST36 + ks * 8 + tq + 4];
                mma16(acc[nt], a0, a1, a2, a3, b0, b1v);
            }
        }

#pragma unroll
        for (int nt = 0; nt < 8; ++nt) {
            int c = nt * 8 + 2 * tq;
            sHh[(r0 + quad) * ST36 + nt * 4 + tq] =
                packh2(fmaxf(acc[nt][0] + sB1[c], 0.f),
                       fmaxf(acc[nt][1] + sB1[c + 1], 0.f));
            sHh[(r0 + quad + 8) * ST36 + nt * 4 + tq] =
                packh2(fmaxf(acc[nt][2] + sB1[c], 0.f),
                       fmaxf(acc[nt][3] + sB1[c + 1], 0.f));
        }
        __syncwarp();

#pragma unroll
        for (int nt = 0; nt < 8; ++nt)
#pragma unroll
            for (int j = 0; j < 4; ++j) acc[nt][j] = 0.f;

#pragma unroll
        for (int ks = 0; ks < 4; ++ks) {
            uint32_t a0 = sHh[(r0 + quad) * ST36 + ks * 8 + tq];
            uint32_t a1 = sHh[(r0 + quad + 8) * ST36 + ks * 8 + tq];
            uint32_t a2 = sHh[(r0 + quad) * ST36 + ks * 8 + tq + 4];
            uint32_t a3 = sHh[(r0 + quad + 8) * ST36 + ks * 8 + tq + 4];
#pragma unroll
            for (int nt = 0; nt < 8; ++nt) {
                uint32_t b0 = sW2t[(nt * 8 + quad) * ST36 + ks * 8 + tq];
                uint32_t b1v = sW2t[(nt * 8 + quad) * ST36 + ks * 8 + tq + 4];
                mma16(acc[nt], a0, a1, a2, a3, b0, b1v);
            }
        }

#pragma unroll
        for (int nt = 0; nt < 8; ++nt) {
            int c = nt * 8 + 2 * tq;
            sHf[(r0 + quad) * SF + c]         = acc[nt][0] + sB2[c];
            sHf[(r0 + quad) * SF + c + 1]     = acc[nt][1] + sB2[c + 1];
            sHf[(r0 + quad + 8) * SF + c]     = acc[nt][2] + sB2[c];
            sHf[(r0 + quad + 8) * SF + c + 1] = acc[nt][3] + sB2[c + 1];
        }
        __syncthreads();

        float racc[8];
#pragma unroll
        for (int j = 0; j < 8; ++j) racc[j] = 0.f;
        int curg = -1;

#pragma unroll
        for (int i = 0; i < 4; ++i) {
            int n = n0 + rr + i;
            if (n < N_NODES) {
                int g = batch[n];
                if (g != curg) {
                    if (curg >= 0) {
                        float* gp = d_gsum + (size_t)curg * (L_LAYERS * HID)
                                    + layer * HID + cc;
                        red4(gp, make_float4(racc[0], racc[1], racc[2], racc[3]));
                        red4(gp + 4, make_float4(racc[4], racc[5], racc[6], racc[7]));
#pragma unroll
                        for (int j = 0; j < 8; ++j) racc[j] = 0.f;
                    }
                    curg = g;
                }
                const float* ev = sHf + (rr + i) * SF + cc;
                float zv[8];
#pragma unroll
                for (int j = 0; j < 8; ++j) {
                    zv[j] = fmaxf(ev[j], 0.f);
                    csum[j] += zv[j];
                    csq[j] += zv[j] * zv[j];
                    racc[j] += zv[j];
                }
                uint4 zo;
                zo.x = packh2(zv[0], zv[1]); zo.y = packh2(zv[2], zv[3]);
                zo.z = packh2(zv[4], zv[5]); zo.w = packh2(zv[6], zv[7]);
                *(uint4*)(d_zh + (size_t)n * 32 + tc * 4) = zo;
            }
        }
        if (curg >= 0) {
            float* gp = d_gsum + (size_t)curg * (L_LAYERS * HID) + layer * HID + cc;
            red4(gp, make_float4(racc[0], racc[1], racc[2], racc[3]));
            red4(gp + 4, make_float4(racc[4], racc[5], racc[6], racc[7]));
        }
    }

    __syncthreads();
#pragma unroll
    for (int j = 0; j < 8; ++j) {
        atomicAdd(&sSum[cc + j], csum[j]);
        atomicAdd(&sSq[cc + j], csq[j]);
    }
    __syncthreads();
    if (tid < 64) {
        atomicAdd(&d_bnsum[layer * 128 + tid], sSum[tid]);
        atomicAdd(&d_bnsum[layer * 128 + 64 + tid], sSq[tid]);
    }
}

// ---------------- per-graph fc0 (+inline BN affine) + scatter ----------------
__global__ __launch_bounds__(64)
void graph_kernel(const float* __restrict__ fc0w, const float* __restrict__ fc0b,
                  const float* __restrict__ gweights, const int* __restrict__ subb,
                  const float* __restrict__ bn_g, const float* __restrict__ bn_b) {
    __shared__ float sG[192];
    __shared__ float sAB[2 * 192];
    int g = blockIdx.x;
    int c = threadIdx.x;

    for (int l = 0; l < L_LAYERS; ++l) {
        float mu = d_bnsum[l * 128 + c] * (1.f / (float)N_NODES);
        float var = d_bnsum[l * 128 + 64 + c] * (1.f / (float)N_NODES) - mu * mu;
        float a = bn_g[l * 64 + c] * rsqrtf(var + BN_EPS);
        sAB[l * 64 + c] = a;
        sAB[192 + l * 64 + c] = bn_b[l * 64 + c] - mu * a;
    }
    __syncthreads();

    float inv = 1.f / fmaxf(d_gcnt[g], 1.f);
    for (int i = c; i < 192; i += 64)
        sG[i] = fmaf(d_gsum[(size_t)g * 192 + i] * inv, sAB[i], sAB[192 + i]);
    __syncthreads();

    float acc = fc0b[c];
    for (int k = 0; k < 192; ++k) acc += sG[k] * fc0w[k * 64 + c];
    float w = gweights[g];
    float v = fmaxf(acc, 0.f) * w;
    int s = subb[g];
    atomicAdd(&d_svec[s * 64 + c], v);
    if (c == 0) atomicAdd(&d_snorm[s], w);
}

// ---------------- subgraph FC layers ----------------
__global__ __launch_bounds__(64)
void fc_kernel(const float* __restrict__ w, const float* __restrict__ b,
               const float* __restrict__ in, float* __restrict__ out,
               int normalize) {
    __shared__ float sR[64];
    int row = blockIdx.x;
    int c = threadIdx.x;
    float v = in[row * 64 + c];
    if (normalize) v = v / fmaxf(d_snorm[row], 1e-12f);
    sR[c] = v;
    __syncthreads();
    float acc = b[c];
    for (int k = 0; k < 64; ++k) acc += sR[k] * w[k * 64 + c];
    out[row * 64 + c] = fmaxf(acc, 0.f);
}

__global__ __launch_bounds__(32)
void pred_kernel(const float* __restrict__ w, const float* __restrict__ b,
                 const float* __restrict__ in, float* __restrict__ out) {
    __shared__ float sR[64];
    int row = blockIdx.x;
    int c = threadIdx.x;
    sR[c] = in[row * 64 + c];
    sR[c + 32] = in[row * 64 + c + 32];
    __syncthreads();
    float acc = b[c];
    for (int k = 0; k < 64; ++k) acc += sR[k] * w[k * 32 + c];
    out[row * 32 + c] = acc;
}

// =====================================================================
extern "C" void kernel_launch(void* const* d_in, const int* in_sizes, int n_in,
                              void* d_out, int out_size) {
    const float* x       = (const float*)d_in[0];
    const int*   eidx    = (const int*)d_in[1];
    const float* eattr   = (const float*)d_in[2];
    const int*   batch   = (const int*)d_in[3];
    const float* weights = (const float*)d_in[4];
    const int*   subb    = (const int*)d_in[5];
    const float* be_w1   = (const float*)d_in[6];
    const float* be_b1   = (const float*)d_in[7];
    const float* be_w2   = (const float*)d_in[8];
    const float* be_b2   = (const float*)d_in[9];
    const float* mlp_w1  = (const float*)d_in[10];
    const float* mlp_b1  = (const float*)d_in[11];
    const float* mlp_w2  = (const float*)d_in[12];
    const float* mlp_b2  = (const float*)d_in[13];
    const float* epsv    = (const float*)d_in[14];
    const float* bn_g    = (const float*)d_in[15];
    const float* bn_b    = (const float*)d_in[16];
    const float* fc0_w   = (const float*)d_in[17];
    const float* fc0_b   = (const float*)d_in[18];
    const float* fc1_w   = (const float*)d_in[19];
    const float* fc1_b   = (const float*)d_in[20];
    const float* fc2_w   = (const float*)d_in[21];
    const float* fc2_b   = (const float*)d_in[22];
    const float* pred_w  = (const float*)d_in[23];
    const float* pred_b  = (const float*)d_in[24];
    float* out = (float*)d_out;

    void *p_agg, *p_bnsum, *p_gsum, *p_gcnt, *p_svec, *p_snorm, *p_t1, *p_t2;
    cudaGetSymbolAddress(&p_agg, d_agg);
    cudaGetSymbolAddress(&p_bnsum, d_bnsum);
    cudaGetSymbolAddress(&p_gsum, d_gsum);
    cudaGetSymbolAddress(&p_gcnt, d_gcnt);
    cudaGetSymbolAddress(&p_svec, d_svec);
    cudaGetSymbolAddress(&p_snorm, d_snorm);
    cudaGetSymbolAddress(&p_t1, d_t1);
    cudaGetSymbolAddress(&p_t2, d_t2);

    cudaFuncSetAttribute(edge_kernel, cudaFuncAttributeMaxDynamicSharedMemorySize,
                         E_SMEM_BYTES);
    cudaFuncSetAttribute(node_kernel, cudaFuncAttributeMaxDynamicSharedMemorySize,
                         N_SMEM_BYTES);

    z_init_kernel<<<(N_NODES * 32) / 256, 256>>>(x);
    cudaMemsetAsync(p_bnsum, 0, L_LAYERS * 2 * HID * sizeof(float));
    cudaMemsetAsync(p_gsum, 0, (size_t)G_GRAPHS * 192 * sizeof(float));
    cudaMemsetAsync(p_gcnt, 0, G_GRAPHS * sizeof(float));
    cudaMemsetAsync(p_svec, 0, S_SUB * HID * sizeof(float));
    cudaMemsetAsync(p_snorm, 0, S_SUB * sizeof(float));
    count_kernel<<<(N_NODES + 255) / 256, 256>>>(batch);

    const float* bnsum = (const float*)p_bnsum;

    for (int l = 0; l < L_LAYERS; ++l) {
        cudaMemsetAsync(p_agg, 0, (size_t)N_NODES * HID * sizeof(float));
        edge_kernel<<<E_GRID, 128, E_SMEM_BYTES>>>(
            eattr, eidx,
            be_w1 + l * EDGE_F * HID, be_b1 + l * HID,
            be_w2 + l * HID * HID,    be_b2 + l * HID,
            bnsum + (l - 1) * 128, bn_g + (l - 1) * HID, bn_b + (l - 1) * HID,
            l > 0 ? 1 : 0);

        node_kernel<<<N_GRID, 128, N_SMEM_BYTES>>>(
            mlp_w1 + l * HID * HID, mlp_b1 + l * HID,
            mlp_w2 + l * HID * HID, mlp_b2 + l * HID,
            epsv + l,
            bnsum + (l - 1) * 128, bn_g + (l - 1) * HID, bn_b + (l - 1) * HID,
            l > 0 ? 1 : 0, l, batch);
    }

    graph_kernel<<<G_GRAPHS, 64>>>(fc0_w, fc0_b, weights, subb, bn_g, bn_b);
    fc_kernel<<<S_SUB, 64>>>(fc1_w, fc1_b, (const float*)p_svec, (float*)p_t1, 1);
    fc_kernel<<<S_SUB, 64>>>(fc2_w, fc2_b, (const float*)p_t1, (float*)p_t2, 0);
    pred_kernel<<<S_SUB, 32>>>(pred_w, pred_b, (const float*)p_t2, out);
}

// round 16
// speedup vs baseline: 1.2354x; 1.2354x over previous
#include <cuda_runtime.h>
#include <cuda_fp16.h>
#include <cstddef>
#include <cstdint>

#define N_NODES 100000
#define N_EDGES 1000000
#define G_GRAPHS 1024
#define S_SUB 128
#define HID 64
#define EDGE_F 32
#define OUT_F 32
#define L_LAYERS 3
#define BN_EPS 1e-5f

#define E_TILE 128
#define E_TILES_TOTAL 7813
#define E_GRID 592             // 148 SMs x 4 blocks: one full wave
#define N_TILES 1563
#define N_GRID 592             // one full wave for node too

#define ST20 20
#define ST36 36
#define SF 68

// ---------------- device scratch ----------------
__device__ uint32_t d_zh[N_NODES * 32];        // node state, half2-packed
__device__ float d_agg[N_NODES * HID];
__device__ float d_bnsum[L_LAYERS * 2 * HID];
__device__ float d_gsum[G_GRAPHS * L_LAYERS * HID];
__device__ float d_gcnt[G_GRAPHS];
__device__ float d_svec[S_SUB * HID];
__device__ float d_snorm[S_SUB];
__device__ float d_t1[S_SUB * HID];
__device__ float d_t2[S_SUB * HID];

__device__ __forceinline__ void red4(float* addr, float4 v) {
    asm volatile("red.global.add.v4.f32 [%0], {%1,%2,%3,%4};"
                 :: "l"(addr), "f"(v.x), "f"(v.y), "f"(v.z), "f"(v.w)
                 : "memory");
}

__device__ __forceinline__ uint32_t packh2(float lo, float hi) {
    __half2 h = __floats2half2_rn(lo, hi);
    return *reinterpret_cast<uint32_t*>(&h);
}

__device__ __forceinline__ float2 unpackh2(uint32_t u) {
    return __half22float2(*reinterpret_cast<__half2*>(&u));
}

__device__ __forceinline__ void mma16(float* d, uint32_t a0, uint32_t a1,
                                      uint32_t a2, uint32_t a3,
                                      uint32_t b0, uint32_t b1) {
    asm volatile(
        "mma.sync.aligned.m16n8k16.row.col.f32.f16.f16.f32 "
        "{%0,%1,%2,%3}, {%4,%5,%6,%7}, {%8,%9}, {%0,%1,%2,%3};"
        : "+f"(d[0]), "+f"(d[1]), "+f"(d[2]), "+f"(d[3])
        : "r"(a0), "r"(a1), "r"(a2), "r"(a3), "r"(b0), "r"(b1));
}

// ---------------- init ----------------
__global__ void count_kernel(const int* __restrict__ batch) {
    int i = blockIdx.x * 256 + threadIdx.x;
    if (i < N_NODES) atomicAdd(&d_gcnt[batch[i]], 1.0f);
}

__global__ void z_init_kernel(const float* __restrict__ x) {
    int i = blockIdx.x * 256 + threadIdx.x;
    float2 v = ((const float2*)x)[i];
    d_zh[i] = packh2(v.x, v.y);
}

// =====================================================================
// Fused edge kernel (round-13 internals; one-wave grid)
// =====================================================================
#define E_SMEM_BYTES ((64*ST20 + 64*ST36 + 256 + 128*ST20 + 128*ST36) * 4)

__global__ __launch_bounds__(128, 4)
void edge_kernel(const float* __restrict__ edge_attr,
                 const int* __restrict__ eidx,
                 const float* __restrict__ w1, const float* __restrict__ b1,
                 const float* __restrict__ w2, const float* __restrict__ b2,
                 const float* __restrict__ bnsum_prev,
                 const float* __restrict__ gamma_prev,
                 const float* __restrict__ beta_prev, int useBN) {
    extern __shared__ float smem[];
    uint32_t* sW1t = (uint32_t*)smem;
    uint32_t* sW2t = sW1t + 64 * ST20;
    float* sB1 = (float*)(sW2t + 64 * ST36);
    float* sB2 = sB1 + 64;
    float* sAB = sB2 + 64;
    uint32_t* sAh = (uint32_t*)(sAB + 128);
    uint32_t* sHh = sAh + 128 * ST20;

    const int tid = threadIdx.x;
    const int lane = tid & 31, warp = tid >> 5;
    const int quad = lane >> 2, tq = lane & 3;
    const int r0 = warp * 32;
    const int tc = tid & 7, tr = tid >> 3;
    const int cc = tc * 8;

    for (int i = tid; i < 1024; i += 128) {
        int n = i & 63, j = i >> 6;
        sW1t[n * ST20 + j] = packh2(w1[(2 * j) * 64 + n], w1[(2 * j + 1) * 64 + n]);
    }
    for (int i = tid; i < 2048; i += 128) {
        int n = i & 63, j = i >> 6;
        sW2t[n * ST36 + j] = packh2(w2[(2 * j) * 64 + n], w2[(2 * j + 1) * 64 + n]);
    }
    if (tid < 64) {
        sB1[tid] = b1[tid]; sB2[tid] = b2[tid];
        float a = 1.f, b = 0.f;
        if (useBN) {
            float mu = bnsum_prev[tid] * (1.f / (float)N_NODES);
            float var = bnsum_prev[64 + tid] * (1.f / (float)N_NODES) - mu * mu;
            a = gamma_prev[tid] * rsqrtf(var + BN_EPS);
            b = beta_prev[tid] - mu * a;
        }
        sAB[tid] = a; sAB[64 + tid] = b;
    }
    __syncthreads();

    const float4 ax0 = *((const float4*)(sAB + cc));
    const float4 ax1 = *((const float4*)(sAB + cc + 4));
    const float4 bx0 = *((const float4*)(sAB + 64 + cc));
    const float4 bx1 = *((const float4*)(sAB + 64 + cc + 4));

    for (int tile = blockIdx.x; tile < E_TILES_TOTAL; tile += E_GRID) {
        const int e0 = tile * E_TILE;

        for (int i = tid; i < 1024; i += 128) {
            int r = i >> 3, q = i & 7;
            float4 v = make_float4(0.f, 0.f, 0.f, 0.f);
            if (e0 + r < N_EDGES)
                v = ((const float4*)(edge_attr + (size_t)(e0 + r) * EDGE_F))[q];
            sAh[r * ST20 + q * 2]     = packh2(v.x, v.y);
            sAh[r * ST20 + q * 2 + 1] = packh2(v.z, v.w);
        }
        __syncthreads();

        float acc[2][8][4];
#pragma unroll
        for (int m = 0; m < 2; ++m)
#pragma unroll
            for (int nt = 0; nt < 8; ++nt)
#pragma unroll
                for (int j = 0; j < 4; ++j) acc[m][nt][j] = 0.f;

#pragma unroll
        for (int ks = 0; ks < 2; ++ks) {
            uint32_t A[2][4];
#pragma unroll
            for (int m = 0; m < 2; ++m) {
                int rb = r0 + 16 * m;
                A[m][0] = sAh[(rb + quad) * ST20 + ks * 8 + tq];
                A[m][1] = sAh[(rb + quad + 8) * ST20 + ks * 8 + tq];
                A[m][2] = sAh[(rb + quad) * ST20 + ks * 8 + tq + 4];
                A[m][3] = sAh[(rb + quad + 8) * ST20 + ks * 8 + tq + 4];
            }
#pragma unroll
            for (int nt = 0; nt < 8; ++nt) {
                uint32_t b0 = sW1t[(nt * 8 + quad) * ST20 + ks * 8 + tq];
                uint32_t b1v = sW1t[(nt * 8 + quad) * ST20 + ks * 8 + tq + 4];
#pragma unroll
                for (int m = 0; m < 2; ++m)
                    mma16(acc[m][nt], A[m][0], A[m][1], A[m][2], A[m][3], b0, b1v);
            }
        }

#pragma unroll
        for (int m = 0; m < 2; ++m) {
            int rb = r0 + 16 * m;
#pragma unroll
            for (int nt = 0; nt < 8; ++nt) {
                int c = nt * 8 + 2 * tq;
                sHh[(rb + quad) * ST36 + nt * 4 + tq] =
                    packh2(fmaxf(acc[m][nt][0] + sB1[c], 0.f),
                           fmaxf(acc[m][nt][1] + sB1[c + 1], 0.f));
                sHh[(rb + quad + 8) * ST36 + nt * 4 + tq] =
                    packh2(fmaxf(acc[m][nt][2] + sB1[c], 0.f),
                           fmaxf(acc[m][nt][3] + sB1[c + 1], 0.f));
            }
        }
        __syncwarp();

#pragma unroll
        for (int m = 0; m < 2; ++m)
#pragma unroll
            for (int nt = 0; nt < 8; ++nt)
#pragma unroll
                for (int j = 0; j < 4; ++j) acc[m][nt][j] = 0.f;

#pragma unroll
        for (int ks = 0; ks < 4; ++ks) {
            uint32_t A[2][4];
#pragma unroll
            for (int m = 0; m < 2; ++m) {
                int rb = r0 + 16 * m;
                A[m][0] = sHh[(rb + quad) * ST36 + ks * 8 + tq];
                A[m][1] = sHh[(rb + quad + 8) * ST36 + ks * 8 + tq];
                A[m][2] = sHh[(rb + quad) * ST36 + ks * 8 + tq + 4];
                A[m][3] = sHh[(rb + quad + 8) * ST36 + ks * 8 + tq + 4];
            }
#pragma unroll
            for (int nt = 0; nt < 8; ++nt) {
                uint32_t b0 = sW2t[(nt * 8 + quad) * ST36 + ks * 8 + tq];
                uint32_t b1v = sW2t[(nt * 8 + quad) * ST36 + ks * 8 + tq + 4];
#pragma unroll
                for (int m = 0; m < 2; ++m)
                    mma16(acc[m][nt], A[m][0], A[m][1], A[m][2], A[m][3], b0, b1v);
            }
        }
        __syncwarp();

#pragma unroll
        for (int m = 0; m < 2; ++m) {
            int rb = r0 + 16 * m;
#pragma unroll
            for (int nt = 0; nt < 8; ++nt) {
                int c = nt * 8 + 2 * tq;
                sHh[(rb + quad) * ST36 + nt * 4 + tq] =
                    packh2(acc[m][nt][0] + sB2[c], acc[m][nt][1] + sB2[c + 1]);
                sHh[(rb + quad + 8) * ST36 + nt * 4 + tq] =
                    packh2(acc[m][nt][2] + sB2[c], acc[m][nt][3] + sB2[c + 1]);
            }
        }
        __syncthreads();

#pragma unroll
        for (int i = 0; i < 8; ++i) {
            int r = tr * 8 + i;
            int e = e0 + r;
            if (e < N_EDGES) {
                int src = eidx[e];
                int dst = eidx[N_EDGES + e];
                uint4 hu = *(const uint4*)(d_zh + (size_t)src * 32 + tc * 4);
                float2 h01 = unpackh2(hu.x), h23 = unpackh2(hu.y);
                float2 h45 = unpackh2(hu.z), h67 = unpackh2(hu.w);
                uint4 eu = *(const uint4*)(sHh + r * ST36 + tc * 4);
                float2 e01 = unpackh2(eu.x), e23 = unpackh2(eu.y);
                float2 e45 = unpackh2(eu.z), e67 = unpackh2(eu.w);
                float4 m0, m1;
                m0.x = fmaxf(fmaf(h01.x, ax0.x, bx0.x) + e01.x, 0.f);
                m0.y = fmaxf(fmaf(h01.y, ax0.y, bx0.y) + e01.y, 0.f);
                m0.z = fmaxf(fmaf(h23.x, ax0.z, bx0.z) + e23.x, 0.f);
                m0.w = fmaxf(fmaf(h23.y, ax0.w, bx0.w) + e23.y, 0.f);
                m1.x = fmaxf(fmaf(h45.x, ax1.x, bx1.x) + e45.x, 0.f);
                m1.y = fmaxf(fmaf(h45.y, ax1.y, bx1.y) + e45.y, 0.f);
                m1.z = fmaxf(fmaf(h67.x, ax1.z, bx1.z) + e67.x, 0.f);
                m1.w = fmaxf(fmaf(h67.y, ax1.w, bx1.w) + e67.y, 0.f);
                red4(d_agg + (size_t)dst * HID + cc, m0);
                red4(d_agg + (size_t)dst * HID + cc + 4, m1);
            }
        }
    }
}

// =====================================================================
// Fused node kernel (round-13 internals; one-wave grid)
// =====================================================================
#define N_SMEM_BYTES ((64*ST36 + 64*ST36 + 256 + 128 + 64*ST36 + 64*ST36 + 64*SF) * 4)

__global__ __launch_bounds__(128)
void node_kernel(const float* __restrict__ w1, const float* __restrict__ b1,
                 const float* __restrict__ w2, const float* __restrict__ b2,
                 const float* __restrict__ epsp,
                 const float* __restrict__ bnsum_prev,
                 const float* __restrict__ gamma_prev,
                 const float* __restrict__ beta_prev, int useBN,
                 int layer, const int* __restrict__ batch) {
    extern __shared__ float smem[];
    uint32_t* sW1t = (uint32_t*)smem;
    uint32_t* sW2t = sW1t + 64 * ST36;
    float* sB1 = (float*)(sW2t + 64 * ST36);
    float* sB2 = sB1 + 64;
    float* sSum = sB2 + 64;
    float* sSq  = sSum + 64;
    float* sAB  = sSq + 64;
    uint32_t* sAh = (uint32_t*)(sAB + 128);
    uint32_t* sHh = sAh + 64 * ST36;
    float* sHf = (float*)(sHh + 64 * ST36);

    const int tid = threadIdx.x;
    const int lane = tid & 31, warp = tid >> 5;
    const int quad = lane >> 2, tq = lane & 3;
    const int r0 = warp * 16;
    const int tc = tid & 7, tr = tid >> 3;
    const int cc = tc * 8, rr = tr * 4;
    const float epl = 1.f + epsp[0];

    for (int i = tid; i < 2048; i += 128) {
        int n = i & 63, j = i >> 6;
        sW1t[n * ST36 + j] = packh2(w1[(2 * j) * 64 + n], w1[(2 * j + 1) * 64 + n]);
    }
    for (int i = tid; i < 2048; i += 128) {
        int n = i & 63, j = i >> 6;
        sW2t[n * ST36 + j] = packh2(w2[(2 * j) * 64 + n], w2[(2 * j + 1) * 64 + n]);
    }
    if (tid < 64) {
        sB1[tid] = b1[tid]; sB2[tid] = b2[tid];
        sSum[tid] = 0.f; sSq[tid] = 0.f;
        float a = 1.f, b = 0.f;
        if (useBN) {
            float mu = bnsum_prev[tid] * (1.f / (float)N_NODES);
            float var = bnsum_prev[64 + tid] * (1.f / (float)N_NODES) - mu * mu;
            a = gamma_prev[tid] * rsqrtf(var + BN_EPS);
            b = beta_prev[tid] - mu * a;
        }
        sAB[tid] = a; sAB[64 + tid] = b;
    }
    __syncthreads();

    float csum[8], csq[8];
#pragma unroll
    for (int j = 0; j < 8; ++j) { csum[j] = 0.f; csq[j] = 0.f; }

    for (int tile = blockIdx.x; tile < N_TILES; tile += N_GRID) {
        const int n0 = tile * 64;

        for (int i = tid; i < 512; i += 128) {
            int r = i >> 3, q = i & 7;
            int n = n0 + r;
            float v[8] = {0.f, 0.f, 0.f, 0.f, 0.f, 0.f, 0.f, 0.f};
            if (n < N_NODES) {
                uint4 zu = ((const uint4*)(d_zh + (size_t)n * 32))[q];
                float2 z01 = unpackh2(zu.x), z23 = unpackh2(zu.y);
                float2 z45 = unpackh2(zu.z), z67 = unpackh2(zu.w);
                float zv[8] = {z01.x, z01.y, z23.x, z23.y,
                               z45.x, z45.y, z67.x, z67.y};
                float4 av0 = ((const float4*)(d_agg + (size_t)n * HID))[q * 2];
                float4 av1 = ((const float4*)(d_agg + (size_t)n * HID))[q * 2 + 1];
                float avv[8] = {av0.x, av0.y, av0.z, av0.w,
                                av1.x, av1.y, av1.z, av1.w};
                const float* aa = sAB + q * 8;
                const float* bb = sAB + 64 + q * 8;
#pragma unroll
                for (int j = 0; j < 8; ++j)
                    v[j] = fmaf(zv[j], epl * aa[j], epl * bb[j]) + avv[j];
            }
            uint32_t* d = sAh + r * ST36 + q * 4;
            d[0] = packh2(v[0], v[1]); d[1] = packh2(v[2], v[3]);
            d[2] = packh2(v[4], v[5]); d[3] = packh2(v[6], v[7]);
        }
        __syncthreads();

        float acc[8][4];
#pragma unroll
        for (int nt = 0; nt < 8; ++nt)
#pragma unroll
            for (int j = 0; j < 4; ++j) acc[nt][j] = 0.f;

#pragma unroll
        for (int ks = 0; ks < 4; ++ks) {
            uint32_t a0 = sAh[(r0 + quad) * ST36 + ks * 8 + tq];
            uint32_t a1 = sAh[(r0 + quad + 8) * ST36 + ks * 8 + tq];
            uint32_t a2 = sAh[(r0 + quad) * ST36 + ks * 8 + tq + 4];
            uint32_t a3 = sAh[(r0 + quad + 8) * ST36 + ks * 8 + tq + 4];
#pragma unroll
            for (int nt = 0; nt < 8; ++nt) {
                uint32_t b0 = sW1t[(nt * 8 + quad) * ST36 + ks * 8 + tq];
                uint32_t b1v = sW1t[(nt * 8 + quad) * ST36 + ks * 8 + tq + 4];
                mma16(acc[nt], a0, a1, a2, a3, b0, b1v);
            }
        }

#pragma unroll
        for (int nt = 0; nt < 8; ++nt) {
            int c = nt * 8 + 2 * tq;
            sHh[(r0 + quad) * ST36 + nt * 4 + tq] =
                packh2(fmaxf(acc[nt][0] + sB1[c], 0.f),
                       fmaxf(acc[nt][1] + sB1[c + 1], 0.f));
            sHh[(r0 + quad + 8) * ST36 + nt * 4 + tq] =
                packh2(fmaxf(acc[nt][2] + sB1[c], 0.f),
                       fmaxf(acc[nt][3] + sB1[c + 1], 0.f));
        }
        __syncwarp();

#pragma unroll
        for (int nt = 0; nt < 8; ++nt)
#pragma unroll
            for (int j = 0; j < 4; ++j) acc[nt][j] = 0.f;

#pragma unroll
        for (int ks = 0; ks < 4; ++ks) {
            uint32_t a0 = sHh[(r0 + quad) * ST36 + ks * 8 + tq];
            uint32_t a1 = sHh[(r0 + quad + 8) * ST36 + ks * 8 + tq];
            uint32_t a2 = sHh[(r0 + quad) * ST36 + ks * 8 + tq + 4];
            uint32_t a3 = sHh[(r0 + quad + 8) * ST36 + ks * 8 + tq + 4];
#pragma unroll
            for (int nt = 0; nt < 8; ++nt) {
                uint32_t b0 = sW2t[(nt * 8 + quad) * ST36 + ks * 8 + tq];
                uint32_t b1v = sW2t[(nt * 8 + quad) * ST36 + ks * 8 + tq + 4];
                mma16(acc[nt], a0, a1, a2, a3, b0, b1v);
            }
        }

#pragma unroll
        for (int nt = 0; nt < 8; ++nt) {
            int c = nt * 8 + 2 * tq;
            sHf[(r0 + quad) * SF + c]         = acc[nt][0] + sB2[c];
            sHf[(r0 + quad) * SF + c + 1]     = acc[nt][1] + sB2[c + 1];
            sHf[(r0 + quad + 8) * SF + c]     = acc[nt][2] + sB2[c];
            sHf[(r0 + quad + 8) * SF + c + 1] = acc[nt][3] + sB2[c + 1];
        }
        __syncthreads();

        float racc[8];
#pragma unroll
        for (int j = 0; j < 8; ++j) racc[j] = 0.f;
        int curg = -1;

#pragma unroll
        for (int i = 0; i < 4; ++i) {
            int n = n0 + rr + i;
            if (n < N_NODES) {
                int g = batch[n];
                if (g != curg) {
                    if (curg >= 0) {
                        float* gp = d_gsum + (size_t)curg * (L_LAYERS * HID)
                                    + layer * HID + cc;
                        red4(gp, make_float4(racc[0], racc[1], racc[2], racc[3]));
                        red4(gp + 4, make_float4(racc[4], racc[5], racc[6], racc[7]));
#pragma unroll
                        for (int j = 0; j < 8; ++j) racc[j] = 0.f;
                    }
                    curg = g;
                }
                const float* ev = sHf + (rr + i) * SF + cc;
                float zv[8];
#pragma unroll
                for (int j = 0; j < 8; ++j) {
                    zv[j] = fmaxf(ev[j], 0.f);
                    csum[j] += zv[j];
                    csq[j] += zv[j] * zv[j];
                    racc[j] += zv[j];
                }
                uint4 zo;
                zo.x = packh2(zv[0], zv[1]); zo.y = packh2(zv[2], zv[3]);
                zo.z = packh2(zv[4], zv[5]); zo.w = packh2(zv[6], zv[7]);
                *(uint4*)(d_zh + (size_t)n * 32 + tc * 4) = zo;
            }
        }
        if (curg >= 0) {
            float* gp = d_gsum + (size_t)curg * (L_LAYERS * HID) + layer * HID + cc;
            red4(gp, make_float4(racc[0], racc[1], racc[2], racc[3]));
            red4(gp + 4, make_float4(racc[4], racc[5], racc[6], racc[7]));
        }
    }

    __syncthreads();
#pragma unroll
    for (int j = 0; j < 8; ++j) {
        atomicAdd(&sSum[cc + j], csum[j]);
        atomicAdd(&sSq[cc + j], csq[j]);
    }
    __syncthreads();
    if (tid < 64) {
        atomicAdd(&d_bnsum[layer * 128 + tid], sSum[tid]);
        atomicAdd(&d_bnsum[layer * 128 + 64 + tid], sSq[tid]);
    }
}

// ---------------- per-graph fc0 (+inline BN affine) + scatter ----------------
__global__ __launch_bounds__(64)
void graph_kernel(const float* __restrict__ fc0w, const float* __restrict__ fc0b,
                  const float* __restrict__ gweights, const int* __restrict__ subb,
                  const float* __restrict__ bn_g, const float* __restrict__ bn_b) {
    __shared__ float sG[192];
    __shared__ float sAB[2 * 192];
    int g = blockIdx.x;
    int c = threadIdx.x;

    for (int l = 0; l < L_LAYERS; ++l) {
        float mu = d_bnsum[l * 128 + c] * (1.f / (float)N_NODES);
        float var = d_bnsum[l * 128 + 64 + c] * (1.f / (float)N_NODES) - mu * mu;
        float a = bn_g[l * 64 + c] * rsqrtf(var + BN_EPS);
        sAB[l * 64 + c] = a;
        sAB[192 + l * 64 + c] = bn_b[l * 64 + c] - mu * a;
    }
    __syncthreads();

    float inv = 1.f / fmaxf(d_gcnt[g], 1.f);
    for (int i = c; i < 192; i += 64)
        sG[i] = fmaf(d_gsum[(size_t)g * 192 + i] * inv, sAB[i], sAB[192 + i]);
    __syncthreads();

    float acc = fc0b[c];
    for (int k = 0; k < 192; ++k) acc += sG[k] * fc0w[k * 64 + c];
    float w = gweights[g];
    float v = fmaxf(acc, 0.f) * w;
    int s = subb[g];
    atomicAdd(&d_svec[s * 64 + c], v);
    if (c == 0) atomicAdd(&d_snorm[s], w);
}

// ---------------- subgraph FC layers ----------------
__global__ __launch_bounds__(64)
void fc_kernel(const float* __restrict__ w, const float* __restrict__ b,
               const float* __restrict__ in, float* __restrict__ out,
               int normalize) {
    __shared__ float sR[64];
    int row = blockIdx.x;
    int c = threadIdx.x;
    float v = in[row * 64 + c];
    if (normalize) v = v / fmaxf(d_snorm[row], 1e-12f);
    sR[c] = v;
    __syncthreads();
    float acc = b[c];
    for (int k = 0; k < 64; ++k) acc += sR[k] * w[k * 64 + c];
    out[row * 64 + c] = fmaxf(acc, 0.f);
}

__global__ __launch_bounds__(32)
void pred_kernel(const float* __restrict__ w, const float* __restrict__ b,
                 const float* __restrict__ in, float* __restrict__ out) {
    __shared__ float sR[64];
    int row = blockIdx.x;
    int c = threadIdx.x;
    sR[c] = in[row * 64 + c];
    sR[c + 32] = in[row * 64 + c + 32];
    __syncthreads();
    float acc = b[c];
    for (int k = 0; k < 64; ++k) acc += sR[k] * w[k * 32 + c];
    out[row * 32 + c] = acc;
}

// =====================================================================
extern "C" void kernel_launch(void* const* d_in, const int* in_sizes, int n_in,
                              void* d_out, int out_size) {
    const float* x       = (const float*)d_in[0];
    const int*   eidx    = (const int*)d_in[1];
    const float* eattr   = (const float*)d_in[2];
    const int*   batch   = (const int*)d_in[3];
    const float* weights = (const float*)d_in[4];
    const int*   subb    = (const int*)d_in[5];
    const float* be_w1   = (const float*)d_in[6];
    const float* be_b1   = (const float*)d_in[7];
    const float* be_w2   = (const float*)d_in[8];
    const float* be_b2   = (const float*)d_in[9];
    const float* mlp_w1  = (const float*)d_in[10];
    const float* mlp_b1  = (const float*)d_in[11];
    const float* mlp_w2  = (const float*)d_in[12];
    const float* mlp_b2  = (const float*)d_in[13];
    const float* epsv    = (const float*)d_in[14];
    const float* bn_g    = (const float*)d_in[15];
    const float* bn_b    = (const float*)d_in[16];
    const float* fc0_w   = (const float*)d_in[17];
    const float* fc0_b   = (const float*)d_in[18];
    const float* fc1_w   = (const float*)d_in[19];
    const float* fc1_b   = (const float*)d_in[20];
    const float* fc2_w   = (const float*)d_in[21];
    const float* fc2_b   = (const float*)d_in[22];
    const float* pred_w  = (const float*)d_in[23];
    const float* pred_b  = (const float*)d_in[24];
    float* out = (float*)d_out;

    void *p_agg, *p_bnsum, *p_gsum, *p_gcnt, *p_svec, *p_snorm, *p_t1, *p_t2;
    cudaGetSymbolAddress(&p_agg, d_agg);
    cudaGetSymbolAddress(&p_bnsum, d_bnsum);
    cudaGetSymbolAddress(&p_gsum, d_gsum);
    cudaGetSymbolAddress(&p_gcnt, d_gcnt);
    cudaGetSymbolAddress(&p_svec, d_svec);
    cudaGetSymbolAddress(&p_snorm, d_snorm);
    cudaGetSymbolAddress(&p_t1, d_t1);
    cudaGetSymbolAddress(&p_t2, d_t2);

    cudaFuncSetAttribute(edge_kernel, cudaFuncAttributeMaxDynamicSharedMemorySize,
                         E_SMEM_BYTES);
    cudaFuncSetAttribute(node_kernel, cudaFuncAttributeMaxDynamicSharedMemorySize,
                         N_SMEM_BYTES);

    z_init_kernel<<<(N_NODES * 32) / 256, 256>>>(x);
    cudaMemsetAsync(p_bnsum, 0, L_LAYERS * 2 * HID * sizeof(float));
    cudaMemsetAsync(p_gsum, 0, (size_t)G_GRAPHS * 192 * sizeof(float));
    cudaMemsetAsync(p_gcnt, 0, G_GRAPHS * sizeof(float));
    cudaMemsetAsync(p_svec, 0, S_SUB * HID * sizeof(float));
    cudaMemsetAsync(p_snorm, 0, S_SUB * sizeof(float));
    count_kernel<<<(N_NODES + 255) / 256, 256>>>(batch);

    const float* bnsum = (const float*)p_bnsum;

    for (int l = 0; l < L_LAYERS; ++l) {
        cudaMemsetAsync(p_agg, 0, (size_t)N_NODES * HID * sizeof(float));
        edge_kernel<<<E_GRID, 128, E_SMEM_BYTES>>>(
            eattr, eidx,
            be_w1 + l * EDGE_F * HID, be_b1 + l * HID,
            be_w2 + l * HID * HID,    be_b2 + l * HID,
            bnsum + (l - 1) * 128, bn_g + (l - 1) * HID, bn_b + (l - 1) * HID,
            l > 0 ? 1 : 0);

        node_kernel<<<N_GRID, 128, N_SMEM_BYTES>>>(
            mlp_w1 + l * HID * HID, mlp_b1 + l * HID,
            mlp_w2 + l * HID * HID, mlp_b2 + l * HID,
            epsv + l,
            bnsum + (l - 1) * 128, bn_g + (l - 1) * HID, bn_b + (l - 1) * HID,
            l > 0 ? 1 : 0, l, batch);
    }

    graph_kernel<<<G_GRAPHS, 64>>>(fc0_w, fc0_b, weights, subb, bn_g, bn_b);
    fc_kernel<<<S_SUB, 64>>>(fc1_w, fc1_b, (const float*)p_svec, (float*)p_t1, 1);
    fc_kernel<<<S_SUB, 64>>>(fc2_w, fc2_b, (const float*)p_t1, (float*)p_t2, 0);
    pred_kernel<<<S_SUB, 32>>>(pred_w, pred_b, (const float*)p_t2, out);
}

// round 17
// speedup vs baseline: 1.2692x; 1.0273x over previous
#include <cuda_runtime.h>
#include <cuda_fp16.h>
#include <cstddef>
#include <cstdint>

#define N_NODES 100000
#define N_EDGES 1000000
#define G_GRAPHS 1024
#define S_SUB 128
#define HID 64
#define EDGE_F 32
#define OUT_F 32
#define L_LAYERS 3
#define BN_EPS 1e-5f

#define E_TILE 128
#define E_TILES_TOTAL 7813
#define E_GRID 740             // 148 SMs x 5 blocks: one full wave
#define N_TILES 1563
#define N_GRID 592             // 148 x 4 (node smem-limited at 4)

#define ST20 20
#define ST36 36
#define SF 68

// ---------------- device scratch ----------------
__device__ uint32_t d_zh[N_NODES * 32];
__device__ float d_agg[N_NODES * HID];
__device__ float d_bnsum[L_LAYERS * 2 * HID];
__device__ float d_gsum[G_GRAPHS * L_LAYERS * HID];
__device__ float d_gcnt[G_GRAPHS];
__device__ float d_svec[S_SUB * HID];
__device__ float d_snorm[S_SUB];

__device__ __forceinline__ void red4(float* addr, float4 v) {
    asm volatile("red.global.add.v4.f32 [%0], {%1,%2,%3,%4};"
                 :: "l"(addr), "f"(v.x), "f"(v.y), "f"(v.z), "f"(v.w)
                 : "memory");
}

__device__ __forceinline__ uint32_t packh2(float lo, float hi) {
    __half2 h = __floats2half2_rn(lo, hi);
    return *reinterpret_cast<uint32_t*>(&h);
}

__device__ __forceinline__ float2 unpackh2(uint32_t u) {
    return __half22float2(*reinterpret_cast<__half2*>(&u));
}

__device__ __forceinline__ void mma16(float* d, uint32_t a0, uint32_t a1,
                                      uint32_t a2, uint32_t a3,
                                      uint32_t b0, uint32_t b1) {
    asm volatile(
        "mma.sync.aligned.m16n8k16.row.col.f32.f16.f16.f32 "
        "{%0,%1,%2,%3}, {%4,%5,%6,%7}, {%8,%9}, {%0,%1,%2,%3};"
        : "+f"(d[0]), "+f"(d[1]), "+f"(d[2]), "+f"(d[3])
        : "r"(a0), "r"(a1), "r"(a2), "r"(a3), "r"(b0), "r"(b1));
}

// ---------------- init ----------------
__global__ void count_kernel(const int* __restrict__ batch) {
    int i = blockIdx.x * 256 + threadIdx.x;
    if (i < N_NODES) atomicAdd(&d_gcnt[batch[i]], 1.0f);
}

__global__ void z_init_kernel(const float* __restrict__ x) {
    int i = blockIdx.x * 256 + threadIdx.x;
    float2 v = ((const float2*)x)[i];
    d_zh[i] = packh2(v.x, v.y);
}

// =====================================================================
// Fused edge kernel: N-half split GEMMs (32 accum regs) -> 5 blocks/SM
// =====================================================================
#define E_SMEM_BYTES ((64*ST20 + 64*ST36 + 256 + 128*ST20 + 128*ST36) * 4)

__global__ __launch_bounds__(128, 5)
void edge_kernel(const float* __restrict__ edge_attr,
                 const int* __restrict__ eidx,
                 const float* __restrict__ w1, const float* __restrict__ b1,
                 const float* __restrict__ w2, const float* __restrict__ b2,
                 const float* __restrict__ bnsum_prev,
                 const float* __restrict__ gamma_prev,
                 const float* __restrict__ beta_prev, int useBN) {
    extern __shared__ float smem[];
    uint32_t* sW1t = (uint32_t*)smem;            // [64][20]
    uint32_t* sW2t = sW1t + 64 * ST20;           // [64][36]
    float* sB1 = (float*)(sW2t + 64 * ST36);
    float* sB2 = sB1 + 64;
    float* sAB = sB2 + 64;                       // [128]
    uint32_t* sAh = (uint32_t*)(sAB + 128);      // [128][20]
    uint32_t* sHh = sAh + 128 * ST20;            // [128][36]

    const int tid = threadIdx.x;
    const int lane = tid & 31, warp = tid >> 5;
    const int quad = lane >> 2, tq = lane & 3;
    const int r0 = warp * 32;
    const int tc = tid & 7, tr = tid >> 3;
    const int cc = tc * 8;

    for (int i = tid; i < 1024; i += 128) {
        int n = i & 63, j = i >> 6;
        sW1t[n * ST20 + j] = packh2(w1[(2 * j) * 64 + n], w1[(2 * j + 1) * 64 + n]);
    }
    for (int i = tid; i < 2048; i += 128) {
        int n = i & 63, j = i >> 6;
        sW2t[n * ST36 + j] = packh2(w2[(2 * j) * 64 + n], w2[(2 * j + 1) * 64 + n]);
    }
    if (tid < 64) {
        sB1[tid] = b1[tid]; sB2[tid] = b2[tid];
        float a = 1.f, b = 0.f;
        if (useBN) {
            float mu = bnsum_prev[tid] * (1.f / (float)N_NODES);
            float var = bnsum_prev[64 + tid] * (1.f / (float)N_NODES) - mu * mu;
            a = gamma_prev[tid] * rsqrtf(var + BN_EPS);
            b = beta_prev[tid] - mu * a;
        }
        sAB[tid] = a; sAB[64 + tid] = b;
    }
    __syncthreads();

    for (int tile = blockIdx.x; tile < E_TILES_TOTAL; tile += E_GRID) {
        const int e0 = tile * E_TILE;

        for (int i = tid; i < 1024; i += 128) {
            int r = i >> 3, q = i & 7;
            float4 v = make_float4(0.f, 0.f, 0.f, 0.f);
            if (e0 + r < N_EDGES)
                v = ((const float4*)(edge_attr + (size_t)(e0 + r) * EDGE_F))[q];
            sAh[r * ST20 + q * 2]     = packh2(v.x, v.y);
            sAh[r * ST20 + q * 2 + 1] = packh2(v.z, v.w);
        }
        __syncthreads();

        // ---- GEMM1 in two N-halves (acc = 32 regs) ----
#pragma unroll
        for (int nh = 0; nh < 2; ++nh) {
            float acc[2][4][4];
#pragma unroll
            for (int m = 0; m < 2; ++m)
#pragma unroll
                for (int nt = 0; nt < 4; ++nt)
#pragma unroll
                    for (int j = 0; j < 4; ++j) acc[m][nt][j] = 0.f;

#pragma unroll
            for (int ks = 0; ks < 2; ++ks) {
                uint32_t A[2][4];
#pragma unroll
                for (int m = 0; m < 2; ++m) {
                    int rb = r0 + 16 * m;
                    A[m][0] = sAh[(rb + quad) * ST20 + ks * 8 + tq];
                    A[m][1] = sAh[(rb + quad + 8) * ST20 + ks * 8 + tq];
                    A[m][2] = sAh[(rb + quad) * ST20 + ks * 8 + tq + 4];
                    A[m][3] = sAh[(rb + quad + 8) * ST20 + ks * 8 + tq + 4];
                }
#pragma unroll
                for (int nt = 0; nt < 4; ++nt) {
                    int nrow = nh * 32 + nt * 8 + quad;
                    uint32_t b0 = sW1t[nrow * ST20 + ks * 8 + tq];
                    uint32_t b1v = sW1t[nrow * ST20 + ks * 8 + tq + 4];
#pragma unroll
                    for (int m = 0; m < 2; ++m)
                        mma16(acc[m][nt], A[m][0], A[m][1], A[m][2], A[m][3], b0, b1v);
                }
            }

#pragma unroll
            for (int m = 0; m < 2; ++m) {
                int rb = r0 + 16 * m;
#pragma unroll
                for (int nt = 0; nt < 4; ++nt) {
                    int c = nh * 32 + nt * 8 + 2 * tq;
                    int uc = nh * 16 + nt * 4 + tq;
                    sHh[(rb + quad) * ST36 + uc] =
                        packh2(fmaxf(acc[m][nt][0] + sB1[c], 0.f),
                               fmaxf(acc[m][nt][1] + sB1[c + 1], 0.f));
                    sHh[(rb + quad + 8) * ST36 + uc] =
                        packh2(fmaxf(acc[m][nt][2] + sB1[c], 0.f),
                               fmaxf(acc[m][nt][3] + sB1[c + 1], 0.f));
                }
            }
        }
        __syncwarp();

        // ---- GEMM2 in two N-halves; e+b2 overwrites sHh after all reads ----
        // First compute both halves' results into registers? No: process
        // half 0 fully (reads all K of own rows), store to a temp region?
        // sHh rows are still needed as A for half 1 -> store results to
        // registers is too big; instead delay stores: compute half into acc,
        // write into sHh only after that half's reads done BUT half 1 still
        // needs original sHh. Solution: store half-0 e_out into the *unused
        // sAh* region (dead after GEMM1), then half-1 in-place, then epilogue
        // reads half0 from sAh, half1 from sHh.
#pragma unroll
        for (int nh = 0; nh < 2; ++nh) {
            float acc[2][4][4];
#pragma unroll
            for (int m = 0; m < 2; ++m)
#pragma unroll
                for (int nt = 0; nt < 4; ++nt)
#pragma unroll
                    for (int j = 0; j < 4; ++j) acc[m][nt][j] = 0.f;

#pragma unroll
            for (int ks = 0; ks < 4; ++ks) {
                uint32_t A[2][4];
#pragma unroll
                for (int m = 0; m < 2; ++m) {
                    int rb = r0 + 16 * m;
                    A[m][0] = sHh[(rb + quad) * ST36 + ks * 8 + tq];
                    A[m][1] = sHh[(rb + quad + 8) * ST36 + ks * 8 + tq];
                    A[m][2] = sHh[(rb + quad) * ST36 + ks * 8 + tq + 4];
                    A[m][3] = sHh[(rb + quad + 8) * ST36 + ks * 8 + tq + 4];
                }
#pragma unroll
                for (int nt = 0; nt < 4; ++nt) {
                    int nrow = nh * 32 + nt * 8 + quad;
                    uint32_t b0 = sW2t[nrow * ST36 + ks * 8 + tq];
                    uint32_t b1v = sW2t[nrow * ST36 + ks * 8 + tq + 4];
#pragma unroll
                    for (int m = 0; m < 2; ++m)
                        mma16(acc[m][nt], A[m][0], A[m][1], A[m][2], A[m][3], b0, b1v);
                }
            }

            if (nh == 0) {
                // half-0 e_out -> sAh (dead), 16 u32 per row
#pragma unroll
                for (int m = 0; m < 2; ++m) {
                    int rb = r0 + 16 * m;
#pragma unroll
                    for (int nt = 0; nt < 4; ++nt) {
                        int c = nt * 8 + 2 * tq;
                        int uc = nt * 4 + tq;
                        sAh[(rb + quad) * ST20 + uc] =
                            packh2(acc[m][nt][0] + sB2[c], acc[m][nt][1] + sB2[c + 1]);
                        sAh[(rb + quad + 8) * ST20 + uc] =
                            packh2(acc[m][nt][2] + sB2[c], acc[m][nt][3] + sB2[c + 1]);
                    }
                }
                __syncwarp();
            } else {
                __syncwarp();   // own-row sHh reads complete before overwrite
#pragma unroll
                for (int m = 0; m < 2; ++m) {
                    int rb = r0 + 16 * m;
#pragma unroll
                    for (int nt = 0; nt < 4; ++nt) {
                        int c = 32 + nt * 8 + 2 * tq;
                        int uc = 16 + nt * 4 + tq;
                        sHh[(rb + quad) * ST36 + uc] =
                            packh2(acc[m][nt][0] + sB2[c], acc[m][nt][1] + sB2[c + 1]);
                        sHh[(rb + quad + 8) * ST36 + uc] =
                            packh2(acc[m][nt][2] + sB2[c], acc[m][nt][3] + sB2[c + 1]);
                    }
                }
            }
        }
        __syncthreads();

        // epilogue: affine from smem, e from sAh (cols<32) / sHh (cols>=32)
        {
            const float4 ax0 = *((const float4*)(sAB + cc));
            const float4 ax1 = *((const float4*)(sAB + cc + 4));
            const float4 bx0 = *((const float4*)(sAB + 64 + cc));
            const float4 bx1 = *((const float4*)(sAB + 64 + cc + 4));
            const int half1 = tc >= 4;   // cols 32..63 live in sHh
#pragma unroll
            for (int i = 0; i < 8; ++i) {
                int r = tr * 8 + i;
                int e = e0 + r;
                if (e < N_EDGES) {
                    int src = eidx[e];
                    int dst = eidx[N_EDGES + e];
                    uint4 hu = *(const uint4*)(d_zh + (size_t)src * 32 + tc * 4);
                    float2 h01 = unpackh2(hu.x), h23 = unpackh2(hu.y);
                    float2 h45 = unpackh2(hu.z), h67 = unpackh2(hu.w);
                    uint4 eu;
                    if (half1)
                        eu = *(const uint4*)(sHh + r * ST36 + 16 + (tc - 4) * 4);
                    else
                        eu = *(const uint4*)(sAh + r * ST20 + tc * 4);
                    float2 e01 = unpackh2(eu.x), e23 = unpackh2(eu.y);
                    float2 e45 = unpackh2(eu.z), e67 = unpackh2(eu.w);
                    float4 m0, m1;
                    m0.x = fmaxf(fmaf(h01.x, ax0.x, bx0.x) + e01.x, 0.f);
                    m0.y = fmaxf(fmaf(h01.y, ax0.y, bx0.y) + e01.y, 0.f);
                    m0.z = fmaxf(fmaf(h23.x, ax0.z, bx0.z) + e23.x, 0.f);
                    m0.w = fmaxf(fmaf(h23.y, ax0.w, bx0.w) + e23.y, 0.f);
                    m1.x = fmaxf(fmaf(h45.x, ax1.x, bx1.x) + e45.x, 0.f);
                    m1.y = fmaxf(fmaf(h45.y, ax1.y, bx1.y) + e45.y, 0.f);
                    m1.z = fmaxf(fmaf(h67.x, ax1.z, bx1.z) + e67.x, 0.f);
                    m1.w = fmaxf(fmaf(h67.y, ax1.w, bx1.w) + e67.y, 0.f);
                    red4(d_agg + (size_t)dst * HID + cc, m0);
                    red4(d_agg + (size_t)dst * HID + cc + 4, m1);
                }
            }
        }
    }
}

// =====================================================================
// Fused node kernel (round-16 winner, unchanged)
// =====================================================================
#define N_SMEM_BYTES ((64*ST36 + 64*ST36 + 256 + 128 + 64*ST36 + 64*ST36 + 64*SF) * 4)

__global__ __launch_bounds__(128)
void node_kernel(const float* __restrict__ w1, const float* __restrict__ b1,
                 const float* __restrict__ w2, const float* __restrict__ b2,
                 const float* __restrict__ epsp,
                 const float* __restrict__ bnsum_prev,
                 const float* __restrict__ gamma_prev,
                 const float* __restrict__ beta_prev, int useBN,
                 int layer, const int* __restrict__ batch) {
    extern __shared__ float smem[];
    uint32_t* sW1t = (uint32_t*)smem;
    uint32_t* sW2t = sW1t + 64 * ST36;
    float* sB1 = (float*)(sW2t + 64 * ST36);
    float* sB2 = sB1 + 64;
    float* sSum = sB2 + 64;
    float* sSq  = sSum + 64;
    float* sAB  = sSq + 64;
    uint32_t* sAh = (uint32_t*)(sAB + 128);
    uint32_t* sHh = sAh + 64 * ST36;
    float* sHf = (float*)(sHh + 64 * ST36);

    const int tid = threadIdx.x;
    const int lane = tid & 31, warp = tid >> 5;
    const int quad = lane >> 2, tq = lane & 3;
    const int r0 = warp * 16;
    const int tc = tid & 7, tr = tid >> 3;
    const int cc = tc * 8, rr = tr * 4;
    const float epl = 1.f + epsp[0];

    for (int i = tid; i < 2048; i += 128) {
        int n = i & 63, j = i >> 6;
        sW1t[n * ST36 + j] = packh2(w1[(2 * j) * 64 + n], w1[(2 * j + 1) * 64 + n]);
    }
    for (int i = tid; i < 2048; i += 128) {
        int n = i & 63, j = i >> 6;
        sW2t[n * ST36 + j] = packh2(w2[(2 * j) * 64 + n], w2[(2 * j + 1) * 64 + n]);
    }
    if (tid < 64) {
        sB1[tid] = b1[tid]; sB2[tid] = b2[tid];
        sSum[tid] = 0.f; sSq[tid] = 0.f;
        float a = 1.f, b = 0.f;
        if (useBN) {
            float mu = bnsum_prev[tid] * (1.f / (float)N_NODES);
            float var = bnsum_prev[64 + tid] * (1.f / (float)N_NODES) - mu * mu;
            a = gamma_prev[tid] * rsqrtf(var + BN_EPS);
            b = beta_prev[tid] - mu * a;
        }
        sAB[tid] = a; sAB[64 + tid] = b;
    }
    __syncthreads();

    float csum[8], csq[8];
#pragma unroll
    for (int j = 0; j < 8; ++j) { csum[j] = 0.f; csq[j] = 0.f; }

    for (int tile = blockIdx.x; tile < N_TILES; tile += N_GRID) {
        const int n0 = tile * 64;

        for (int i = tid; i < 512; i += 128) {
            int r = i >> 3, q = i & 7;
            int n = n0 + r;
            float v[8] = {0.f, 0.f, 0.f, 0.f, 0.f, 0.f, 0.f, 0.f};
            if (n < N_NODES) {
                uint4 zu = ((const uint4*)(d_zh + (size_t)n * 32))[q];
                float2 z01 = unpackh2(zu.x), z23 = unpackh2(zu.y);
                float2 z45 = unpackh2(zu.z), z67 = unpackh2(zu.w);
                float zv[8] = {z01.x, z01.y, z23.x, z23.y,
                               z45.x, z45.y, z67.x, z67.y};
                float4 av0 = ((const float4*)(d_agg + (size_t)n * HID))[q * 2];
                float4 av1 = ((const float4*)(d_agg + (size_t)n * HID))[q * 2 + 1];
                float avv[8] = {av0.x, av0.y, av0.z, av0.w,
                                av1.x, av1.y, av1.z, av1.w};
                const float* aa = sAB + q * 8;
                const float* bb = sAB + 64 + q * 8;
#pragma unroll
                for (int j = 0; j < 8; ++j)
                    v[j] = fmaf(zv[j], epl * aa[j], epl * bb[j]) + avv[j];
            }
            uint32_t* d = sAh + r * ST36 + q * 4;
            d[0] = packh2(v[0], v[1]); d[1] = packh2(v[2], v[3]);
            d[2] = packh2(v[4], v[5]); d[3] = packh2(v[6], v[7]);
        }
        __syncthreads();

        float acc[8][4];
#pragma unroll
        for (int nt = 0; nt < 8; ++nt)
#pragma unroll
            for (int j = 0; j < 4; ++j) acc[nt][j] = 0.f;

#pragma unroll
        for (int ks = 0; ks < 4; ++ks) {
            uint32_t a0 = sAh[(r0 + quad) * ST36 + ks * 8 + tq];
            uint32_t a1 = sAh[(r0 + quad + 8) * ST36 + ks * 8 + tq];
            uint32_t a2 = sAh[(r0 + quad) * ST36 + ks * 8 + tq + 4];
            uint32_t a3 = sAh[(r0 + quad + 8) * ST36 + ks * 8 + tq + 4];
#pragma unroll
            for (int nt = 0; nt < 8; ++nt) {
                uint32_t b0 = sW1t[(nt * 8 + quad) * ST36 + ks * 8 + tq];
                uint32_t b1v = sW1t[(nt * 8 + quad) * ST36 + ks * 8 + tq + 4];
                mma16(acc[nt], a0, a1, a2, a3, b0, b1v);
            }
        }

#pragma unroll
        for (int nt = 0; nt < 8; ++nt) {
            int c = nt * 8 + 2 * tq;
            sHh[(r0 + quad) * ST36 + nt * 4 + tq] =
                packh2(fmaxf(acc[nt][0] + sB1[c], 0.f),
                       fmaxf(acc[nt][1] + sB1[c + 1], 0.f));
            sHh[(r0 + quad + 8) * ST36 + nt * 4 + tq] =
                packh2(fmaxf(acc[nt][2] + sB1[c], 0.f),
                       fmaxf(acc[nt][3] + sB1[c + 1], 0.f));
        }
        __syncwarp();

#pragma unroll
        for (int nt = 0; nt < 8; ++nt)
#pragma unroll
            for (int j = 0; j < 4; ++j) acc[nt][j] = 0.f;

#pragma unroll
        for (int ks = 0; ks < 4; ++ks) {
            uint32_t a0 = sHh[(r0 + quad) * ST36 + ks * 8 + tq];
            uint32_t a1 = sHh[(r0 + quad + 8) * ST36 + ks * 8 + tq];
            uint32_t a2 = sHh[(r0 + quad) * ST36 + ks * 8 + tq + 4];
            uint32_t a3 = sHh[(r0 + quad + 8) * ST36 + ks * 8 + tq + 4];
#pragma unroll
            for (int nt = 0; nt < 8; ++nt) {
                uint32_t b0 = sW2t[(nt * 8 + quad) * ST36 + ks * 8 + tq];
                uint32_t b1v = sW2t[(nt * 8 + quad) * ST36 + ks * 8 + tq + 4];
                mma16(acc[nt], a0, a1, a2, a3, b0, b1v);
            }
        }

#pragma unroll
        for (int nt = 0; nt < 8; ++nt) {
            int c = nt * 8 + 2 * tq;
            sHf[(r0 + quad) * SF + c]         = acc[nt][0] + sB2[c];
            sHf[(r0 + quad) * SF + c + 1]     = acc[nt][1] + sB2[c + 1];
            sHf[(r0 + quad + 8) * SF + c]     = acc[nt][2] + sB2[c];
            sHf[(r0 + quad + 8) * SF + c + 1] = acc[nt][3] + sB2[c + 1];
        }
        __syncthreads();

        float racc[8];
#pragma unroll
        for (int j = 0; j < 8; ++j) racc[j] = 0.f;
        int curg = -1;

#pragma unroll
        for (int i = 0; i < 4; ++i) {
            int n = n0 + rr + i;
            if (n < N_NODES) {
                int g = batch[n];
                if (g != curg) {
                    if (curg >= 0) {
                        float* gp = d_gsum + (size_t)curg * (L_LAYERS * HID)
                                    + layer * HID + cc;
                        red4(gp, make_float4(racc[0], racc[1], racc[2], racc[3]));
                        red4(gp + 4, make_float4(racc[4], racc[5], racc[6], racc[7]));
#pragma unroll
                        for (int j = 0; j < 8; ++j) racc[j] = 0.f;
                    }
                    curg = g;
                }
                const float* ev = sHf + (rr + i) * SF + cc;
                float zv[8];
#pragma unroll
                for (int j = 0; j < 8; ++j) {
                    zv[j] = fmaxf(ev[j], 0.f);
                    csum[j] += zv[j];
                    csq[j] += zv[j] * zv[j];
                    racc[j] += zv[j];
                }
                uint4 zo;
                zo.x = packh2(zv[0], zv[1]); zo.y = packh2(zv[2], zv[3]);
                zo.z = packh2(zv[4], zv[5]); zo.w = packh2(zv[6], zv[7]);
                *(uint4*)(d_zh + (size_t)n * 32 + tc * 4) = zo;
            }
        }
        if (curg >= 0) {
            float* gp = d_gsum + (size_t)curg * (L_LAYERS * HID) + layer * HID + cc;
            red4(gp, make_float4(racc[0], racc[1], racc[2], racc[3]));
            red4(gp + 4, make_float4(racc[4], racc[5], racc[6], racc[7]));
        }
    }

    __syncthreads();
#pragma unroll
    for (int j = 0; j < 8; ++j) {
        atomicAdd(&sSum[cc + j], csum[j]);
        atomicAdd(&sSq[cc + j], csq[j]);
    }
    __syncthreads();
    if (tid < 64) {
        atomicAdd(&d_bnsum[layer * 128 + tid], sSum[tid]);
        atomicAdd(&d_bnsum[layer * 128 + 64 + tid], sSq[tid]);
    }
}

// ---------------- per-graph fc0 (+inline BN affine) + scatter ----------------
__global__ __launch_bounds__(64)
void graph_kernel(const float* __restrict__ fc0w, const float* __restrict__ fc0b,
                  const float* __restrict__ gweights, const int* __restrict__ subb,
                  const float* __restrict__ bn_g, const float* __restrict__ bn_b) {
    __shared__ float sG[192];
    __shared__ float sAB[2 * 192];
    int g = blockIdx.x;
    int c = threadIdx.x;

    for (int l = 0; l < L_LAYERS; ++l) {
        float mu = d_bnsum[l * 128 + c] * (1.f / (float)N_NODES);
        float var = d_bnsum[l * 128 + 64 + c] * (1.f / (float)N_NODES) - mu * mu;
        float a = bn_g[l * 64 + c] * rsqrtf(var + BN_EPS);
        sAB[l * 64 + c] = a;
        sAB[192 + l * 64 + c] = bn_b[l * 64 + c] - mu * a;
    }
    __syncthreads();

    float inv = 1.f / fmaxf(d_gcnt[g], 1.f);
    for (int i = c; i < 192; i += 64)
        sG[i] = fmaf(d_gsum[(size_t)g * 192 + i] * inv, sAB[i], sAB[192 + i]);
    __syncthreads();

    float acc = fc0b[c];
    for (int k = 0; k < 192; ++k) acc += sG[k] * fc0w[k * 64 + c];
    float w = gweights[g];
    float v = fmaxf(acc, 0.f) * w;
    int s = subb[g];
    atomicAdd(&d_svec[s * 64 + c], v);
    if (c == 0) atomicAdd(&d_snorm[s], w);
}

// ---------------- fused subgraph tail: fc1 -> fc2 -> pred ----------------
__global__ __launch_bounds__(64)
void tail_kernel(const float* __restrict__ fc1w, const float* __restrict__ fc1b,
                 const float* __restrict__ fc2w, const float* __restrict__ fc2b,
                 const float* __restrict__ predw, const float* __restrict__ predb,
                 float* __restrict__ out) {
    __shared__ float sA[64];
    __shared__ float sB[64];
    int row = blockIdx.x;
    int c = threadIdx.x;

    sA[c] = d_svec[row * 64 + c] / fmaxf(d_snorm[row], 1e-12f);
    __syncthreads();
    float acc = fc1b[c];
    for (int k = 0; k < 64; ++k) acc += sA[k] * fc1w[k * 64 + c];
    sB[c] = fmaxf(acc, 0.f);
    __syncthreads();
    acc = fc2b[c];
    for (int k = 0; k < 64; ++k) acc += sB[k] * fc2w[k * 64 + c];
    sA[c] = fmaxf(acc, 0.f);
    __syncthreads();
    if (c < OUT_F) {
        acc = predb[c];
        for (int k = 0; k < 64; ++k) acc += sA[k] * predw[k * OUT_F + c];
        out[row * OUT_F + c] = acc;
    }
}

// =====================================================================
extern "C" void kernel_launch(void* const* d_in, const int* in_sizes, int n_in,
                              void* d_out, int out_size) {
    const float* x       = (const float*)d_in[0];
    const int*   eidx    = (const int*)d_in[1];
    const float* eattr   = (const float*)d_in[2];
    const int*   batch   = (const int*)d_in[3];
    const float* weights = (const float*)d_in[4];
    const int*   subb    = (const int*)d_in[5];
    const float* be_w1   = (const float*)d_in[6];
    const float* be_b1   = (const float*)d_in[7];
    const float* be_w2   = (const float*)d_in[8];
    const float* be_b2   = (const float*)d_in[9];
    const float* mlp_w1  = (const float*)d_in[10];
    const float* mlp_b1  = (const float*)d_in[11];
    const float* mlp_w2  = (const float*)d_in[12];
    const float* mlp_b2  = (const float*)d_in[13];
    const float* epsv    = (const float*)d_in[14];
    const float* bn_g    = (const float*)d_in[15];
    const float* bn_b    = (const float*)d_in[16];
    const float* fc0_w   = (const float*)d_in[17];
    const float* fc0_b   = (const float*)d_in[18];
    const float* fc1_w   = (const float*)d_in[19];
    const float* fc1_b   = (const float*)d_in[20];
    const float* fc2_w   = (const float*)d_in[21];
    const float* fc2_b   = (const float*)d_in[22];
    const float* pred_w  = (const float*)d_in[23];
    const float* pred_b  = (const float*)d_in[24];
    float* out = (float*)d_out;

    void *p_agg, *p_bnsum, *p_gsum, *p_gcnt, *p_svec, *p_snorm;
    cudaGetSymbolAddress(&p_agg, d_agg);
    cudaGetSymbolAddress(&p_bnsum, d_bnsum);
    cudaGetSymbolAddress(&p_gsum, d_gsum);
    cudaGetSymbolAddress(&p_gcnt, d_gcnt);
    cudaGetSymbolAddress(&p_svec, d_svec);
    cudaGetSymbolAddress(&p_snorm, d_snorm);

    cudaFuncSetAttribute(edge_kernel, cudaFuncAttributeMaxDynamicSharedMemorySize,
                         E_SMEM_BYTES);
    cudaFuncSetAttribute(node_kernel, cudaFuncAttributeMaxDynamicSharedMemorySize,
                         N_SMEM_BYTES);

    z_init_kernel<<<(N_NODES * 32) / 256, 256>>>(x);
    cudaMemsetAsync(p_bnsum, 0, L_LAYERS * 2 * HID * sizeof(float));
    cudaMemsetAsync(p_gsum, 0, (size_t)G_GRAPHS * 192 * sizeof(float));
    cudaMemsetAsync(p_gcnt, 0, G_GRAPHS * sizeof(float));
    cudaMemsetAsync(p_svec, 0, S_SUB * HID * sizeof(float));
    cudaMemsetAsync(p_snorm, 0, S_SUB * sizeof(float));
    count_kernel<<<(N_NODES + 255) / 256, 256>>>(batch);

    const float* bnsum = (const float*)p_bnsum;

    for (int l = 0; l < L_LAYERS; ++l) {
        cudaMemsetAsync(p_agg, 0, (size_t)N_NODES * HID * sizeof(float));
        edge_kernel<<<E_GRID, 128, E_SMEM_BYTES>>>(
            eattr, eidx,
            be_w1 + l * EDGE_F * HID, be_b1 + l * HID,
            be_w2 + l * HID * HID,    be_b2 + l * HID,
            bnsum + (l - 1) * 128, bn_g + (l - 1) * HID, bn_b + (l - 1) * HID,
            l > 0 ? 1 : 0);

        node_kernel<<<N_GRID, 128, N_SMEM_BYTES>>>(
            mlp_w1 + l * HID * HID, mlp_b1 + l * HID,
            mlp_w2 + l * HID * HID, mlp_b2 + l * HID,
            epsv + l,
            bnsum + (l - 1) * 128, bn_g + (l - 1) * HID, bn_b + (l - 1) * HID,
            l > 0 ? 1 : 0, l, batch);
    }

    graph_kernel<<<G_GRAPHS, 64>>>(fc0_w, fc0_b, weights, subb, bn_g, bn_b);
    tail_kernel<<<S_SUB, 64>>>(fc1_w, fc1_b, fc2_w, fc2_b, pred_w, pred_b, out);
}